// round 6
// baseline (speedup 1.0000x reference)
#include <cuda_runtime.h>
#include <cuda_bf16.h>
#include <cstdint>

// Problem constants (shape-fixed problem)
#define BB 2
#define LL 1024
#define D_SEQ 21
#define D_EMB 64
#define D_MODEL 128
#define ROWS (BB * LL)           // 2048

// Per-symbol separable tables (seq values are in [0, 21)).
__device__ float4 g_TP[D_SEQ * (D_MODEL / 4)];   // T_P[s,d] = bias[d] + sum_c emb[s,c]*W[d,c]
__device__ float4 g_TQ[D_SEQ * (D_MODEL / 4)];   // T_Q[s,d] = sum_c emb[s,c]*W[d,64+c]
__device__ float4 g_W128[D_MODEL / 4];           // packed W[:,128] column

// ---------------------------------------------------------------------------
// Kernel 1: per-symbol table precompute. 21 blocks x 128 threads.
// ---------------------------------------------------------------------------
__global__ __launch_bounds__(128) void table_kernel(
    const float* __restrict__ emb,     // [21, 64]
    const float* __restrict__ W,       // [128, 129] row-major
    const float* __restrict__ bias)    // [128]
{
    const int s = blockIdx.x;          // symbol 0..20
    const int d = threadIdx.x;         // 0..127

    __shared__ float e[D_EMB];
    if (d < D_EMB) e[d] = emb[s * D_EMB + d];
    __syncthreads();

    const float* wrow = W + d * 129;
    float accP = bias[d];
    float accQ = 0.0f;
#pragma unroll
    for (int c = 0; c < D_EMB; c++) {
        accP = fmaf(e[c], wrow[c], accP);
        accQ = fmaf(e[c], wrow[D_EMB + c], accQ);
    }
    ((float*)g_TP)[s * D_MODEL + d] = accP;
    ((float*)g_TQ)[s * D_MODEL + d] = accQ;
    if (s == 0) ((float*)g_W128)[d] = wrow[2 * D_EMB];   // W[d, 128]
}

// ---------------------------------------------------------------------------
// Kernel 2: out[b,i,j,d] = T_P[seq_i,d] + T_Q[seq_j,d] + log(|idx_i-idx_j|+1)*W128[d]
// TWO rows (i0 = 2*blk, i1 = 2*blk+1) per block: halves block count, halves
// sQ staging, and reuses each Q/seq/idx fetch for two output stores.
// 256 threads = 8 warps; warp w owns j in [w*128, (w+1)*128).
// Lane t owns float4 d = 4t..4t+3.
// ---------------------------------------------------------------------------
#define NWARP 8
#define JPW (LL / NWARP)      // 128 j's per warp

__global__ __launch_bounds__(256) void pair_kernel(
    const int* __restrict__ seq,
    const int* __restrict__ idx,
    float4* __restrict__ out)
{
    const int row0 = blockIdx.x * 2;        // b*L + i0 (row1 = row0+1, same batch)
    const int row1 = row0 + 1;
    const int b = row0 >> 10;
    const int w = threadIdx.x >> 5;
    const int t = threadIdx.x & 31;

    __shared__ float4 sQ[D_SEQ * 32];       // 10.75 KB
    for (int k = threadIdx.x; k < D_SEQ * 32; k += 256) sQ[k] = g_TQ[k];
    __syncthreads();

    const float4 p0 = g_TP[__ldg(seq + row0) * 32 + t];
    const float4 p1 = g_TP[__ldg(seq + row1) * 32 + t];
    const float4 w4 = g_W128[t];
    const int idx_i0 = __ldg(idx + row0);
    const int idx_i1 = __ldg(idx + row1);

    const int* __restrict__ idxb = idx + b * LL;
    const int* __restrict__ seqb = seq + b * LL;
    float4* __restrict__ out0 = out + (size_t)row0 * LL * 32;
    float4* __restrict__ out1 = out + (size_t)row1 * LL * 32;

    const int j0 = w * JPW;
#pragma unroll 4
    for (int k = 0; k < JPW; k++) {
        const int j = j0 + k;
        const int sj = __ldg(seqb + j);
        const int idx_j = __ldg(idxb + j);
        const float4 q = sQ[sj * 32 + t];
        const float s0 = __logf(fabsf((float)(idx_i0 - idx_j)) + 1.0f);
        const float s1 = __logf(fabsf((float)(idx_i1 - idx_j)) + 1.0f);
        float4 o0, o1;
        o0.x = fmaf(s0, w4.x, p0.x + q.x);
        o0.y = fmaf(s0, w4.y, p0.y + q.y);
        o0.z = fmaf(s0, w4.z, p0.z + q.z);
        o0.w = fmaf(s0, w4.w, p0.w + q.w);
        o1.x = fmaf(s1, w4.x, p1.x + q.x);
        o1.y = fmaf(s1, w4.y, p1.y + q.y);
        o1.z = fmaf(s1, w4.z, p1.z + q.z);
        o1.w = fmaf(s1, w4.w, p1.w + q.w);
        __stcs(&out0[(size_t)j * 32 + t], o0);
        __stcs(&out1[(size_t)j * 32 + t], o1);
    }
}

// ---------------------------------------------------------------------------
// Launch: inputs per metadata order: seq(int32), idx(int32), emb_table(f32),
// W(f32 [128,129]), b(f32 [128]). Output: f32 [2,1024,1024,128].
// ---------------------------------------------------------------------------
extern "C" void kernel_launch(void* const* d_in, const int* in_sizes, int n_in,
                              void* d_out, int out_size)
{
    const int*   seq  = (const int*)d_in[0];
    const int*   idx  = (const int*)d_in[1];
    const float* emb  = (const float*)d_in[2];
    const float* W    = (const float*)d_in[3];
    const float* bias = (const float*)d_in[4];
    float4* out = (float4*)d_out;

    table_kernel<<<D_SEQ, 128>>>(emb, W, bias);
    pair_kernel<<<ROWS / 2, 256>>>(seq, idx, out);
}

// round 7
// speedup vs baseline: 1.0224x; 1.0224x over previous
#include <cuda_runtime.h>
#include <cuda_bf16.h>
#include <cstdint>

// Problem constants (shape-fixed problem)
#define BB 2
#define LL 1024
#define D_SEQ 21
#define D_EMB 64
#define D_MODEL 128
#define ROWS (BB * LL)           // 2048

// Per-symbol separable tables (seq values are in [0, 21)).
__device__ float4 g_TP[D_SEQ * (D_MODEL / 4)];   // T_P[s,d] = bias[d] + sum_c emb[s,c]*W[d,c]
__device__ float4 g_TQ[D_SEQ * (D_MODEL / 4)];   // T_Q[s,d] = sum_c emb[s,c]*W[d,64+c]
__device__ float4 g_W128[D_MODEL / 4];           // packed W[:,128] column

// ---------------------------------------------------------------------------
// Kernel 1: per-symbol table precompute. 21 blocks x 128 threads.
// Triggers programmatic launch completion so pair_kernel can start early.
// ---------------------------------------------------------------------------
__global__ __launch_bounds__(128) void table_kernel(
    const float* __restrict__ emb,     // [21, 64]
    const float* __restrict__ W,       // [128, 129] row-major
    const float* __restrict__ bias)    // [128]
{
    const int s = blockIdx.x;          // symbol 0..20
    const int d = threadIdx.x;         // 0..127

    __shared__ float e[D_EMB];
    if (d < D_EMB) e[d] = emb[s * D_EMB + d];
    __syncthreads();

    const float* wrow = W + d * 129;
    float accP = bias[d];
    float accQ = 0.0f;
#pragma unroll
    for (int c = 0; c < D_EMB; c++) {
        accP = fmaf(e[c], wrow[c], accP);
        accQ = fmaf(e[c], wrow[D_EMB + c], accQ);
    }
    ((float*)g_TP)[s * D_MODEL + d] = accP;
    ((float*)g_TQ)[s * D_MODEL + d] = accQ;
    if (s == 0) ((float*)g_W128)[d] = wrow[2 * D_EMB];   // W[d, 128]

#if __CUDA_ARCH__ >= 900
    cudaTriggerProgrammaticLaunchCompletion();
#endif
}

// ---------------------------------------------------------------------------
// Kernel 2: out[b,i,j,d] = T_P[seq_i,d] + T_Q[seq_j,d] + log(|idx_i-idx_j|+1)*W128[d]
// One block per (b,i) row (R2 structure — best measured). 256 thr = 8 warps,
// warp w owns j in [w*128,(w+1)*128), lane t owns float4 d = 4t..4t+3.
// __launch_bounds__(256, 8) forces regs<=32 -> 8 blocks/SM for store MLP.
// PDL: table-independent setup first, then grid-dependency sync, then tables.
// ---------------------------------------------------------------------------
#define NWARP 8
#define JPW (LL / NWARP)      // 128 j's per warp

__global__ __launch_bounds__(256, 8) void pair_kernel(
    const int* __restrict__ seq,
    const int* __restrict__ idx,
    float4* __restrict__ out)
{
    const int rowi = blockIdx.x;            // b*L + i
    const int b = rowi >> 10;
    const int w = threadIdx.x >> 5;
    const int t = threadIdx.x & 31;

    // Table-independent setup (inputs only).
    const int idx_i = __ldg(idx + rowi);
    const int si = __ldg(seq + rowi);
    const int* __restrict__ idxb = idx + b * LL;
    const int* __restrict__ seqb = seq + b * LL;
    float4* __restrict__ outb = out + (size_t)rowi * LL * 32;

#if __CUDA_ARCH__ >= 900
    cudaGridDependencySynchronize();        // wait for table_kernel results
#endif

    __shared__ float4 sQ[D_SEQ * 32];       // 10.75 KB
    for (int k = threadIdx.x; k < D_SEQ * 32; k += 256) sQ[k] = g_TQ[k];
    __syncthreads();

    const float4 p4 = g_TP[si * 32 + t];
    const float4 w4 = g_W128[t];

    const int j0 = w * JPW;
#pragma unroll 4
    for (int k = 0; k < JPW; k++) {
        const int j = j0 + k;
        const int sj = __ldg(seqb + j);
        const int idx_j = __ldg(idxb + j);
        const float s = __logf(fabsf((float)(idx_i - idx_j)) + 1.0f);
        const float4 q = sQ[sj * 32 + t];
        float4 o;
        o.x = fmaf(s, w4.x, p4.x + q.x);
        o.y = fmaf(s, w4.y, p4.y + q.y);
        o.z = fmaf(s, w4.z, p4.z + q.z);
        o.w = fmaf(s, w4.w, p4.w + q.w);
        __stcs(&outb[(size_t)j * 32 + t], o);
    }
}

// ---------------------------------------------------------------------------
// Launch: inputs per metadata order: seq(int32), idx(int32), emb_table(f32),
// W(f32 [128,129]), b(f32 [128]). Output: f32 [2,1024,1024,128].
// pair_kernel launched with programmatic stream serialization (PDL) so it
// overlaps table_kernel's tail + launch latency.
// ---------------------------------------------------------------------------
extern "C" void kernel_launch(void* const* d_in, const int* in_sizes, int n_in,
                              void* d_out, int out_size)
{
    const int*   seq  = (const int*)d_in[0];
    const int*   idx  = (const int*)d_in[1];
    const float* emb  = (const float*)d_in[2];
    const float* W    = (const float*)d_in[3];
    const float* bias = (const float*)d_in[4];
    float4* out = (float4*)d_out;

    table_kernel<<<D_SEQ, 128>>>(emb, W, bias);

    cudaLaunchConfig_t cfg = {};
    cfg.gridDim = dim3(ROWS, 1, 1);
    cfg.blockDim = dim3(256, 1, 1);
    cfg.dynamicSmemBytes = 0;
    cfg.stream = 0;
    cudaLaunchAttribute attrs[1];
    attrs[0].id = cudaLaunchAttributeProgrammaticStreamSerialization;
    attrs[0].val.programmaticStreamSerializationAllowed = 1;
    cfg.attrs = attrs;
    cfg.numAttrs = 1;
    cudaLaunchKernelEx(&cfg, pair_kernel, seq, idx, out);
}

// round 11
// speedup vs baseline: 1.0467x; 1.0239x over previous
#include <cuda_runtime.h>
#include <cuda_bf16.h>
#include <cstdint>

// Problem constants (shape-fixed problem)
#define BB 2
#define LL 1024
#define D_SEQ 21
#define D_EMB 64
#define D_MODEL 128
#define ROWS (BB * LL)           // 2048

// Per-symbol separable tables (seq values are in [0, 21)).
__device__ float4 g_TP[D_SEQ * (D_MODEL / 4)];   // T_P[s,d] = bias[d] + sum_c emb[s,c]*W[d,c]
__device__ float4 g_TQ[D_SEQ * (D_MODEL / 4)];   // T_Q[s,d] = sum_c emb[s,c]*W[d,64+c]
__device__ float4 g_W128[D_MODEL / 4];           // packed W[:,128] column

// ---------------------------------------------------------------------------
// Kernel 1: per-symbol table precompute. 21 blocks x 128 threads.
// Triggers programmatic launch completion so pair_kernel can start early.
// ---------------------------------------------------------------------------
__global__ __launch_bounds__(128) void table_kernel(
    const float* __restrict__ emb,     // [21, 64]
    const float* __restrict__ W,       // [128, 129] row-major
    const float* __restrict__ bias)    // [128]
{
    const int s = blockIdx.x;          // symbol 0..20
    const int d = threadIdx.x;         // 0..127

    __shared__ float e[D_EMB];
    if (d < D_EMB) e[d] = emb[s * D_EMB + d];
    __syncthreads();

    const float* wrow = W + d * 129;
    float accP = bias[d];
    float accQ = 0.0f;
#pragma unroll
    for (int c = 0; c < D_EMB; c++) {
        accP = fmaf(e[c], wrow[c], accP);
        accQ = fmaf(e[c], wrow[D_EMB + c], accQ);
    }
    ((float*)g_TP)[s * D_MODEL + d] = accP;
    ((float*)g_TQ)[s * D_MODEL + d] = accQ;
    if (s == 0) ((float*)g_W128)[d] = wrow[2 * D_EMB];   // W[d, 128]

#if __CUDA_ARCH__ >= 900
    cudaTriggerProgrammaticLaunchCompletion();
#endif
}

// ---------------------------------------------------------------------------
// Kernel 2: out[b,i,j,d] = T_P[seq_i,d] + T_Q[seq_j,d] + log(|idx_i-idx_j|+1)*W128[d]
// R2 structure (measured best: 159.1us, DRAM 80.3%): one block per (b,i) row,
// 256 threads = 8 warps; warp w owns j in [w*128,(w+1)*128); lane t owns
// float4 d = 4t..4t+3. T_Q staged in smem; log recomputed in-loop (cheaper
// than staging). NO min-blocks clause: ptxas's free choice (40 regs, 6
// blocks/SM) produces the best-scheduled loop body.
// ---------------------------------------------------------------------------
#define NWARP 8
#define JPW (LL / NWARP)      // 128 j's per warp

__global__ __launch_bounds__(256) void pair_kernel(
    const int* __restrict__ seq,
    const int* __restrict__ idx,
    float4* __restrict__ out)
{
    const int rowi = blockIdx.x;            // b*L + i
    const int b = rowi >> 10;
    const int w = threadIdx.x >> 5;
    const int t = threadIdx.x & 31;

    // Table-independent setup (reads inputs only).
    const int idx_i = __ldg(idx + rowi);
    const int si = __ldg(seq + rowi);
    const int* __restrict__ idxb = idx + b * LL;
    const int* __restrict__ seqb = seq + b * LL;
    float4* __restrict__ outb = out + (size_t)rowi * LL * 32;

#if __CUDA_ARCH__ >= 900
    cudaGridDependencySynchronize();        // wait for table_kernel results
#endif

    __shared__ float4 sQ[D_SEQ * 32];       // 10.75 KB
    for (int k = threadIdx.x; k < D_SEQ * 32; k += 256) sQ[k] = g_TQ[k];
    __syncthreads();

    const float4 p4 = g_TP[si * 32 + t];
    const float4 w4 = g_W128[t];

    const int j0 = w * JPW;
#pragma unroll 4
    for (int k = 0; k < JPW; k++) {
        const int j = j0 + k;
        const int sj = __ldg(seqb + j);
        const int idx_j = __ldg(idxb + j);
        const float s = __logf(fabsf((float)(idx_i - idx_j)) + 1.0f);
        const float4 q = sQ[sj * 32 + t];
        float4 o;
        o.x = fmaf(s, w4.x, p4.x + q.x);
        o.y = fmaf(s, w4.y, p4.y + q.y);
        o.z = fmaf(s, w4.z, p4.z + q.z);
        o.w = fmaf(s, w4.w, p4.w + q.w);
        __stcs(&outb[(size_t)j * 32 + t], o);
    }
}

// ---------------------------------------------------------------------------
// Launch: inputs per metadata order: seq(int32), idx(int32), emb_table(f32),
// W(f32 [128,129]), b(f32 [128]). Output: f32 [2,1024,1024,128].
// pair_kernel launched with programmatic stream serialization (PDL) so it
// overlaps table_kernel's execution + launch latency.
// ---------------------------------------------------------------------------
extern "C" void kernel_launch(void* const* d_in, const int* in_sizes, int n_in,
                              void* d_out, int out_size)
{
    const int*   seq  = (const int*)d_in[0];
    const int*   idx  = (const int*)d_in[1];
    const float* emb  = (const float*)d_in[2];
    const float* W    = (const float*)d_in[3];
    const float* bias = (const float*)d_in[4];
    float4* out = (float4*)d_out;

    table_kernel<<<D_SEQ, 128>>>(emb, W, bias);

    cudaLaunchConfig_t cfg = {};
    cfg.gridDim = dim3(ROWS, 1, 1);
    cfg.blockDim = dim3(256, 1, 1);
    cfg.dynamicSmemBytes = 0;
    cfg.stream = 0;
    cudaLaunchAttribute attrs[1];
    attrs[0].id = cudaLaunchAttributeProgrammaticStreamSerialization;
    attrs[0].val.programmaticStreamSerializationAllowed = 1;
    cfg.attrs = attrs;
    cfg.numAttrs = 1;
    cudaLaunchKernelEx(&cfg, pair_kernel, seq, idx, out);
}

// round 12
// speedup vs baseline: 1.1360x; 1.0852x over previous
#include <cuda_runtime.h>
#include <cuda_bf16.h>
#include <cstdint>

// Problem constants (shape-fixed problem)
#define BB 2
#define LL 1024
#define D_SEQ 21
#define D_EMB 64
#define D_MODEL 128
#define ROWS (BB * LL)           // 2048

// Per-symbol separable tables (seq values are in [0, 21)).
__device__ float4 g_TP[D_SEQ * (D_MODEL / 4)];   // T_P[s,d] = bias[d] + sum_c emb[s,c]*W[d,c]
__device__ float4 g_TQ[D_SEQ * (D_MODEL / 4)];   // T_Q[s,d] = sum_c emb[s,c]*W[d,64+c]
__device__ float4 g_W128[D_MODEL / 4];           // packed W[:,128] column

// ---------------------------------------------------------------------------
// Kernel 1: per-symbol table precompute. 21 blocks x 128 threads.
// ---------------------------------------------------------------------------
__global__ __launch_bounds__(128) void table_kernel(
    const float* __restrict__ emb,     // [21, 64]
    const float* __restrict__ W,       // [128, 129] row-major
    const float* __restrict__ bias)    // [128]
{
    const int s = blockIdx.x;          // symbol 0..20
    const int d = threadIdx.x;         // 0..127

    __shared__ float e[D_EMB];
    if (d < D_EMB) e[d] = emb[s * D_EMB + d];
    __syncthreads();

    const float* wrow = W + d * 129;
    float accP = bias[d];
    float accQ = 0.0f;
#pragma unroll
    for (int c = 0; c < D_EMB; c++) {
        accP = fmaf(e[c], wrow[c], accP);
        accQ = fmaf(e[c], wrow[D_EMB + c], accQ);
    }
    ((float*)g_TP)[s * D_MODEL + d] = accP;
    ((float*)g_TQ)[s * D_MODEL + d] = accQ;
    if (s == 0) ((float*)g_W128)[d] = wrow[2 * D_EMB];   // W[d, 128]
}

// ---------------------------------------------------------------------------
// Kernel 2: out[b,i,j,d] = T_P[seq_i,d] + T_Q[seq_j,d] + log(|idx_i-idx_j|+1)*W128[d]
// Quarter-row blocks: grid = ROWS*4; block (rowi, chunk) owns j in
// [chunk*256, chunk*256+256). 256 threads = 8 warps; warp w owns 32 j's;
// lane t owns float4 d = 4t..4t+3. Hot loop identical to the measured best
// (R11: 157.5us, regs=40). Finer blocks (~17us) shrink the DRAM-idle tail
// that 68us blocks produced at 2.3 waves.
// ---------------------------------------------------------------------------
#define NWARP 8
#define NCHUNK 4
#define JPB (LL / NCHUNK)       // 256 j's per block
#define JPW (JPB / NWARP)       // 32 j's per warp

__global__ __launch_bounds__(256) void pair_kernel(
    const int* __restrict__ seq,
    const int* __restrict__ idx,
    float4* __restrict__ out)
{
    const int blk = blockIdx.x;
    const int rowi = blk >> 2;              // b*L + i
    const int chunk = blk & (NCHUNK - 1);
    const int b = rowi >> 10;
    const int w = threadIdx.x >> 5;
    const int t = threadIdx.x & 31;

    // Setup (reads inputs only).
    const int idx_i = __ldg(idx + rowi);
    const int si = __ldg(seq + rowi);
    const int* __restrict__ idxb = idx + b * LL;
    const int* __restrict__ seqb = seq + b * LL;
    float4* __restrict__ outb = out + (size_t)rowi * LL * 32;

    __shared__ float4 sQ[D_SEQ * 32];       // 10.75 KB
    for (int k = threadIdx.x; k < D_SEQ * 32; k += 256) sQ[k] = g_TQ[k];
    __syncthreads();

    const float4 p4 = g_TP[si * 32 + t];
    const float4 w4 = g_W128[t];

    const int j0 = chunk * JPB + w * JPW;
#pragma unroll 4
    for (int k = 0; k < JPW; k++) {
        const int j = j0 + k;
        const int sj = __ldg(seqb + j);
        const int idx_j = __ldg(idxb + j);
        const float s = __logf(fabsf((float)(idx_i - idx_j)) + 1.0f);
        const float4 q = sQ[sj * 32 + t];
        float4 o;
        o.x = fmaf(s, w4.x, p4.x + q.x);
        o.y = fmaf(s, w4.y, p4.y + q.y);
        o.z = fmaf(s, w4.z, p4.z + q.z);
        o.w = fmaf(s, w4.w, p4.w + q.w);
        __stcs(&outb[(size_t)j * 32 + t], o);
    }
}

// ---------------------------------------------------------------------------
// Launch: inputs per metadata order: seq(int32), idx(int32), emb_table(f32),
// W(f32 [128,129]), b(f32 [128]). Output: f32 [2,1024,1024,128].
// ---------------------------------------------------------------------------
extern "C" void kernel_launch(void* const* d_in, const int* in_sizes, int n_in,
                              void* d_out, int out_size)
{
    const int*   seq  = (const int*)d_in[0];
    const int*   idx  = (const int*)d_in[1];
    const float* emb  = (const float*)d_in[2];
    const float* W    = (const float*)d_in[3];
    const float* bias = (const float*)d_in[4];
    float4* out = (float4*)d_out;

    table_kernel<<<D_SEQ, 128>>>(emb, W, bias);
    pair_kernel<<<ROWS * NCHUNK, 256>>>(seq, idx, out);
}